// round 4
// baseline (speedup 1.0000x reference)
#include <cuda_runtime.h>

// ResamplerLayer: trilinear resample of [B,D,H,W,C] fp32 volume at
// [B,OD,OH,OW,3] continuous coords (ZERO boundary per reference: weights use
// CLAMPED corner indices). Output [B,OD,OH,OW,C] fp32.
//
// B=2, D=H=W=128, C=4, OD=OH=OW=96.

#define Bk   2
#define Dk   128
#define Hk   128
#define Wk   128
#define Ck   4
#define ODk  96
#define OHk  96
#define OWk  96

#define NPTS (Bk * ODk * OHk * OWk)          // 1,769,472
#define PTS_PER_BATCH (ODk * OHk * OWk)      // 884,736

__device__ __forceinline__ float4 f4_fma2(float4 a, float wa, float4 b, float wb) {
    // a*wa + b*wb, elementwise
    float4 r;
    r.x = fmaf(a.x, wa, b.x * wb);
    r.y = fmaf(a.y, wa, b.y * wb);
    r.z = fmaf(a.z, wa, b.z * wb);
    r.w = fmaf(a.w, wa, b.w * wb);
    return r;
}

__global__ __launch_bounds__(256)
void resampler_kernel(const float4* __restrict__ vol,     // [B,D,H,W] of float4 (C=4)
                      const float*  __restrict__ coords,  // [N,3]
                      float4*       __restrict__ out)     // [N] of float4
{
    int idx = blockIdx.x * blockDim.x + threadIdx.x;
    if (idx >= NPTS) return;

    int b = idx / PTS_PER_BATCH;

    const float* cp = coords + (size_t)idx * 3;
    float cd = __ldg(cp + 0);   // D coord
    float ch = __ldg(cp + 1);   // H coord
    float cw = __ldg(cp + 2);   // W coord

    // floor / ceil with replicate clamp (reference: clip((int)floor, 0, S-1),
    // clip((int)(floor+1), 0, S-1)); weights from the CLAMPED ints.
    int fd0 = (int)floorf(cd);
    int fh0 = (int)floorf(ch);
    int fw0 = (int)floorf(cw);

    int fd = min(max(fd0, 0), Dk - 1);
    int fh = min(max(fh0, 0), Hk - 1);
    int fw = min(max(fw0, 0), Wk - 1);
    int cdI = min(max(fd0 + 1, 0), Dk - 1);
    int chI = min(max(fh0 + 1, 0), Hk - 1);
    int cwI = min(max(fw0 + 1, 0), Wk - 1);

    float w0d = cd - (float)fd;   // weight for ceil side (bit=1)
    float w1d = (float)cdI - cd;  // weight for floor side (bit=0)
    float w0h = ch - (float)fh;
    float w1h = (float)chI - ch;
    float w0w = cw - (float)fw;
    float w1w = (float)cwI - cw;

    // Base offsets in float4 units: ((b*D + d)*H + h)*W + w
    int base   = b * (Dk * Hk * Wk);
    int rowF_dF = base + (fd  * Hk + fh ) * Wk;   // d=floor, h=floor
    int rowF_dC = base + (cdI * Hk + fh ) * Wk;   // d=ceil,  h=floor
    int rowC_dF = base + (fd  * Hk + chI) * Wk;   // d=floor, h=ceil
    int rowC_dC = base + (cdI * Hk + chI) * Wk;   // d=ceil,  h=ceil

    // 8 independent gathers (MLP=8) — bits (d,h,w): 0 = floor side.
    float4 s000 = __ldg(vol + rowF_dF + fw);
    float4 s001 = __ldg(vol + rowF_dF + cwI);
    float4 s010 = __ldg(vol + rowC_dF + fw);
    float4 s011 = __ldg(vol + rowC_dF + cwI);
    float4 s100 = __ldg(vol + rowF_dC + fw);
    float4 s101 = __ldg(vol + rowF_dC + cwI);
    float4 s110 = __ldg(vol + rowC_dC + fw);
    float4 s111 = __ldg(vol + rowC_dC + cwI);

    // Blend along W (bit=0 -> w1, bit=1 -> w0), then H, then D.
    float4 c00 = f4_fma2(s000, w1w, s001, w0w);
    float4 c01 = f4_fma2(s010, w1w, s011, w0w);
    float4 c10 = f4_fma2(s100, w1w, s101, w0w);
    float4 c11 = f4_fma2(s110, w1w, s111, w0w);

    float4 c0 = f4_fma2(c00, w1h, c01, w0h);
    float4 c1 = f4_fma2(c10, w1h, c11, w0h);

    float4 r = f4_fma2(c0, w1d, c1, w0d);

    out[idx] = r;
}

extern "C" void kernel_launch(void* const* d_in, const int* in_sizes, int n_in,
                              void* d_out, int out_size) {
    const float4* vol    = (const float4*)d_in[0];   // inputs [B,D,H,W,C=4] fp32
    const float*  coords = (const float*)d_in[1];    // sample_coords [B,OD,OH,OW,3]
    float4*       out    = (float4*)d_out;

    const int threads = 256;
    const int blocks  = (NPTS + threads - 1) / threads;
    resampler_kernel<<<blocks, threads>>>(vol, coords, out);
}

// round 6
// speedup vs baseline: 1.0781x; 1.0781x over previous
#include <cuda_runtime.h>

// ResamplerLayer: trilinear resample of [B,D,H,W,C=4] fp32 volume at
// [B,OD,OH,OW,3] continuous coords (ZERO boundary: weights from CLAMPED
// corner indices). Output [B,OD,OH,OW,4] fp32.
//
// Optimization (R4): 2 lanes per point. Lane bit selects floor-W vs ceil-W,
// so the adjacent W-pair lands in the SAME warp gather instruction and
// coalesces into one L1tex wavefront (same 128B line with prob 7/8).
// Per-point gather wavefronts: 8 -> ~4.5.

#define Bk   2
#define Dk   128
#define Hk   128
#define Wk   128
#define ODk  96
#define OHk  96
#define OWk  96

#define NPTS (Bk * ODk * OHk * OWk)          // 1,769,472
#define PTS_PER_BATCH (ODk * OHk * OWk)      // 884,736
#define NTHREADS_TOTAL (NPTS * 2)            // 3,538,944 = 13824 * 256 exactly

__device__ __forceinline__ float4 f4_fma2(float4 a, float wa, float4 b, float wb) {
    float4 r;
    r.x = fmaf(a.x, wa, b.x * wb);
    r.y = fmaf(a.y, wa, b.y * wb);
    r.z = fmaf(a.z, wa, b.z * wb);
    r.w = fmaf(a.w, wa, b.w * wb);
    return r;
}

__global__ __launch_bounds__(256)
void resampler_kernel(const float4* __restrict__ vol,     // [B,D,H,W] of float4
                      const float*  __restrict__ coords,  // [NPTS,3]
                      float4*       __restrict__ out)     // [NPTS] of float4
{
    int t = blockIdx.x * blockDim.x + threadIdx.x;        // exact-fit grid, no guard
    int p = t >> 1;                                       // point index
    int s = t & 1;                                        // 0 = floor-W, 1 = ceil-W

    int b = p / PTS_PER_BATCH;

    const float* cp = coords + (size_t)p * 3;
    float cd = __ldg(cp + 0);   // D coord
    float ch = __ldg(cp + 1);   // H coord
    float cw = __ldg(cp + 2);   // W coord

    int fd0 = (int)floorf(cd);
    int fh0 = (int)floorf(ch);
    int fw0 = (int)floorf(cw);

    int fd  = min(max(fd0,     0), Dk - 1);
    int fh  = min(max(fh0,     0), Hk - 1);
    int fw  = min(max(fw0,     0), Wk - 1);
    int cdI = min(max(fd0 + 1, 0), Dk - 1);
    int chI = min(max(fh0 + 1, 0), Hk - 1);
    int cwI = min(max(fw0 + 1, 0), Wk - 1);

    // Weights from CLAMPED ints (reference's ZERO-boundary semantics).
    float w0d = cd - (float)fd;    // ceil-side weight
    float w1d = (float)cdI - cd;   // floor-side weight
    float w0h = ch - (float)fh;
    float w1h = (float)chI - ch;
    float w0w = cw - (float)fw;
    float w1w = (float)cwI - cw;

    int wsel = s ? cwI : fw;       // this lane's W index

    int base = b * (Dk * Hk * Wk);
    const float4* q = vol + base + wsel;

    int rFF = (fd  * Hk + fh ) * Wk;   // d=floor, h=floor
    int rCF = (cdI * Hk + fh ) * Wk;   // d=ceil,  h=floor
    int rFC = (fd  * Hk + chI) * Wk;   // d=floor, h=ceil
    int rCC = (cdI * Hk + chI) * Wk;   // d=ceil,  h=ceil

    // 4 independent gathers per lane; the lane pair's addresses are 16B apart
    // within each instruction -> shared 128B line -> coalesced wavefront.
    float4 sFF = __ldg(q + rFF);
    float4 sCF = __ldg(q + rCF);
    float4 sFC = __ldg(q + rFC);
    float4 sCC = __ldg(q + rCC);

    // Bilinear blend over H then D at this lane's fixed W.
    float4 e0 = f4_fma2(sFF, w1h, sFC, w0h);   // d = floor
    float4 e1 = f4_fma2(sCF, w1h, sCC, w0h);   // d = ceil
    float4 c  = f4_fma2(e0, w1d, e1, w0d);

    // Exchange with partner lane and do the final W blend on the even lane.
    float4 o;
    o.x = __shfl_xor_sync(0xffffffffu, c.x, 1);
    o.y = __shfl_xor_sync(0xffffffffu, c.y, 1);
    o.z = __shfl_xor_sync(0xffffffffu, c.z, 1);
    o.w = __shfl_xor_sync(0xffffffffu, c.w, 1);

    if (s == 0) {
        // mine = floor-W sample (weight w1w), partner = ceil-W (weight w0w)
        float4 r = f4_fma2(c, w1w, o, w0w);
        out[p] = r;
    }
}

extern "C" void kernel_launch(void* const* d_in, const int* in_sizes, int n_in,
                              void* d_out, int out_size) {
    const float4* vol    = (const float4*)d_in[0];   // inputs [B,D,H,W,4] fp32
    const float*  coords = (const float*)d_in[1];    // sample_coords [B,OD,OH,OW,3]
    float4*       out    = (float4*)d_out;

    const int threads = 256;
    const int blocks  = NTHREADS_TOTAL / threads;    // exact fit
    resampler_kernel<<<blocks, threads>>>(vol, coords, out);
}

// round 7
// speedup vs baseline: 1.1147x; 1.0340x over previous
#include <cuda_runtime.h>

// ResamplerLayer: trilinear resample of [B,D,H,W,C=4] fp32 volume at
// [B,OD,OH,OW,3] continuous coords (ZERO boundary: weights from CLAMPED
// corner indices). Output [B,OD,OH,OW,4] fp32.
//
// R4: 2 lanes per point; lane bit selects floor-W vs ceil-W so the adjacent
//     W-pair coalesces into one L1tex wavefront per gather instruction.
// R6: 2 points per thread (point q in batch 0, point q+PTS_PER_BATCH in
//     batch 1) -> 8 independent gathers in flight per lane (MLP back to 8)
//     while keeping the pairing trick. Kernel was latency-bound (no SOL>65%).

#define Bk   2
#define Dk   128
#define Hk   128
#define Wk   128
#define ODk  96
#define OHk  96
#define OWk  96

#define NPTS (Bk * ODk * OHk * OWk)          // 1,769,472
#define PTS_PER_BATCH (ODk * OHk * OWk)      // 884,736 == NPTS/2
#define VOLSZ (Dk * Hk * Wk)

__device__ __forceinline__ float4 f4_fma2(float4 a, float wa, float4 b, float wb) {
    float4 r;
    r.x = fmaf(a.x, wa, b.x * wb);
    r.y = fmaf(a.y, wa, b.y * wb);
    r.z = fmaf(a.z, wa, b.z * wb);
    r.w = fmaf(a.w, wa, b.w * wb);
    return r;
}

struct PtAddr {
    const float4* q;   // volume base + batch + this lane's W
    int rFF, rCF, rFC, rCC;
    float w0d, w1d, w0h, w1h, w0w, w1w;
};

__device__ __forceinline__ PtAddr make_addr(const float4* __restrict__ vol,
                                            const float* __restrict__ coords,
                                            int p, int batch_base, int s) {
    const float* cp = coords + (size_t)p * 3;
    float cd = __ldg(cp + 0);
    float ch = __ldg(cp + 1);
    float cw = __ldg(cp + 2);

    int fd0 = (int)floorf(cd);
    int fh0 = (int)floorf(ch);
    int fw0 = (int)floorf(cw);

    int fd  = min(max(fd0,     0), Dk - 1);
    int fh  = min(max(fh0,     0), Hk - 1);
    int fw  = min(max(fw0,     0), Wk - 1);
    int cdI = min(max(fd0 + 1, 0), Dk - 1);
    int chI = min(max(fh0 + 1, 0), Hk - 1);
    int cwI = min(max(fw0 + 1, 0), Wk - 1);

    PtAddr a;
    a.w0d = cd - (float)fd;    a.w1d = (float)cdI - cd;
    a.w0h = ch - (float)fh;    a.w1h = (float)chI - ch;
    a.w0w = cw - (float)fw;    a.w1w = (float)cwI - cw;

    int wsel = s ? cwI : fw;
    a.q = vol + batch_base + wsel;
    a.rFF = (fd  * Hk + fh ) * Wk;
    a.rCF = (cdI * Hk + fh ) * Wk;
    a.rFC = (fd  * Hk + chI) * Wk;
    a.rCC = (cdI * Hk + chI) * Wk;
    return a;
}

__global__ __launch_bounds__(256)
void resampler_kernel(const float4* __restrict__ vol,     // [B,D,H,W] of float4
                      const float*  __restrict__ coords,  // [NPTS,3]
                      float4*       __restrict__ out)     // [NPTS] of float4
{
    int t = blockIdx.x * blockDim.x + threadIdx.x;        // exact-fit grid
    int q = t >> 1;                                       // pair index in [0, NPTS/2)
    int s = t & 1;                                        // 0 = floor-W, 1 = ceil-W

    int p0 = q;                    // batch 0
    int p1 = q + PTS_PER_BATCH;    // batch 1 (same spatial offset)

    PtAddr a0 = make_addr(vol, coords, p0, 0,     s);
    PtAddr a1 = make_addr(vol, coords, p1, VOLSZ, s);

    // Issue all 8 gathers back-to-back: MLP=8 per lane. Lane pair addresses
    // are 16B apart within each instruction -> shared 128B line wavefront.
    float4 s0FF = __ldg(a0.q + a0.rFF);
    float4 s0CF = __ldg(a0.q + a0.rCF);
    float4 s0FC = __ldg(a0.q + a0.rFC);
    float4 s0CC = __ldg(a0.q + a0.rCC);
    float4 s1FF = __ldg(a1.q + a1.rFF);
    float4 s1CF = __ldg(a1.q + a1.rCF);
    float4 s1FC = __ldg(a1.q + a1.rFC);
    float4 s1CC = __ldg(a1.q + a1.rCC);

    // Point 0: bilinear H,D at fixed W, exchange, W-blend.
    float4 e0 = f4_fma2(s0FF, a0.w1h, s0FC, a0.w0h);
    float4 e1 = f4_fma2(s0CF, a0.w1h, s0CC, a0.w0h);
    float4 c0 = f4_fma2(e0, a0.w1d, e1, a0.w0d);

    float4 o0;
    o0.x = __shfl_xor_sync(0xffffffffu, c0.x, 1);
    o0.y = __shfl_xor_sync(0xffffffffu, c0.y, 1);
    o0.z = __shfl_xor_sync(0xffffffffu, c0.z, 1);
    o0.w = __shfl_xor_sync(0xffffffffu, c0.w, 1);

    // Point 1.
    float4 f0 = f4_fma2(s1FF, a1.w1h, s1FC, a1.w0h);
    float4 f1 = f4_fma2(s1CF, a1.w1h, s1CC, a1.w0h);
    float4 c1 = f4_fma2(f0, a1.w1d, f1, a1.w0d);

    float4 o1;
    o1.x = __shfl_xor_sync(0xffffffffu, c1.x, 1);
    o1.y = __shfl_xor_sync(0xffffffffu, c1.y, 1);
    o1.z = __shfl_xor_sync(0xffffffffu, c1.z, 1);
    o1.w = __shfl_xor_sync(0xffffffffu, c1.w, 1);

    if (s == 0) {
        out[p0] = f4_fma2(c0, a0.w1w, o0, a0.w0w);
        out[p1] = f4_fma2(c1, a1.w1w, o1, a1.w0w);
    }
}

extern "C" void kernel_launch(void* const* d_in, const int* in_sizes, int n_in,
                              void* d_out, int out_size) {
    const float4* vol    = (const float4*)d_in[0];   // inputs [B,D,H,W,4] fp32
    const float*  coords = (const float*)d_in[1];    // sample_coords [B,OD,OH,OW,3]
    float4*       out    = (float4*)d_out;

    const int threads = 256;
    const int blocks  = NPTS / threads;              // NPTS threads total, exact fit
    resampler_kernel<<<blocks, threads>>>(vol, coords, out);
}

// round 9
// speedup vs baseline: 1.2704x; 1.1396x over previous
#include <cuda_runtime.h>

// ResamplerLayer: trilinear resample of [B,D,H,W,C=4] fp32 volume at
// [B,OD,OH,OW,3] continuous coords (ZERO boundary: weights from CLAMPED
// corner indices). Output [B,OD,OH,OW,4] fp32.
//
// R4: 2 lanes per point (lane bit = floor-W / ceil-W) -> adjacent 16B pair
//     coalesces into one L1tex wavefront per gather instruction.
// R6: 2 points per thread (batch 0 + batch 1 at same spatial offset) -> 8
//     independent gathers in flight per lane.
// R7/R8: L2 eviction-priority hints via createpolicy + L2::cache_hint
//     (ptxas rejects the inline evict qualifier on 128-bit loads).
//     Volume loads: evict_last (pin the 67MB volume in 126MB L2).
//     Coords: evict_first. Output stores: st.global.cs (streaming).

#define Bk   2
#define Dk   128
#define Hk   128
#define Wk   128
#define ODk  96
#define OHk  96
#define OWk  96

#define NPTS (Bk * ODk * OHk * OWk)          // 1,769,472
#define PTS_PER_BATCH (ODk * OHk * OWk)      // 884,736 == NPTS/2
#define VOLSZ (Dk * Hk * Wk)

__device__ __forceinline__ unsigned long long pol_evict_last() {
    unsigned long long p;
    asm("createpolicy.fractional.L2::evict_last.b64 %0, 1.0;" : "=l"(p));
    return p;
}

__device__ __forceinline__ unsigned long long pol_evict_first() {
    unsigned long long p;
    asm("createpolicy.fractional.L2::evict_first.b64 %0, 1.0;" : "=l"(p));
    return p;
}

// Volume gather: non-coherent load, pinned in L2 (evict_last policy).
__device__ __forceinline__ float4 ldg_vol(const float4* p, unsigned long long pol) {
    float4 v;
    asm volatile("ld.global.nc.L2::cache_hint.v4.f32 {%0,%1,%2,%3}, [%4], %5;"
                 : "=f"(v.x), "=f"(v.y), "=f"(v.z), "=f"(v.w)
                 : "l"(p), "l"(pol));
    return v;
}

// Coord load: streaming (evict_first policy).
__device__ __forceinline__ float ldg_coord(const float* p, unsigned long long pol) {
    float v;
    asm volatile("ld.global.nc.L2::cache_hint.f32 %0, [%1], %2;"
                 : "=f"(v) : "l"(p), "l"(pol));
    return v;
}

// Output store: cache-streaming.
__device__ __forceinline__ void stg_out(float4* p, float4 v) {
    asm volatile("st.global.cs.v4.f32 [%0], {%1,%2,%3,%4};"
                 :: "l"(p), "f"(v.x), "f"(v.y), "f"(v.z), "f"(v.w) : "memory");
}

__device__ __forceinline__ float4 f4_fma2(float4 a, float wa, float4 b, float wb) {
    float4 r;
    r.x = fmaf(a.x, wa, b.x * wb);
    r.y = fmaf(a.y, wa, b.y * wb);
    r.z = fmaf(a.z, wa, b.z * wb);
    r.w = fmaf(a.w, wa, b.w * wb);
    return r;
}

struct PtAddr {
    const float4* q;   // volume base + batch + this lane's W
    int rFF, rCF, rFC, rCC;
    float w0d, w1d, w0h, w1h, w0w, w1w;
};

__device__ __forceinline__ PtAddr make_addr(const float4* __restrict__ vol,
                                            const float* __restrict__ coords,
                                            int p, int batch_base, int s,
                                            unsigned long long polF) {
    const float* cp = coords + (size_t)p * 3;
    float cd = ldg_coord(cp + 0, polF);
    float ch = ldg_coord(cp + 1, polF);
    float cw = ldg_coord(cp + 2, polF);

    int fd0 = (int)floorf(cd);
    int fh0 = (int)floorf(ch);
    int fw0 = (int)floorf(cw);

    int fd  = min(max(fd0,     0), Dk - 1);
    int fh  = min(max(fh0,     0), Hk - 1);
    int fw  = min(max(fw0,     0), Wk - 1);
    int cdI = min(max(fd0 + 1, 0), Dk - 1);
    int chI = min(max(fh0 + 1, 0), Hk - 1);
    int cwI = min(max(fw0 + 1, 0), Wk - 1);

    PtAddr a;
    a.w0d = cd - (float)fd;    a.w1d = (float)cdI - cd;
    a.w0h = ch - (float)fh;    a.w1h = (float)chI - ch;
    a.w0w = cw - (float)fw;    a.w1w = (float)cwI - cw;

    int wsel = s ? cwI : fw;
    a.q = vol + batch_base + wsel;
    a.rFF = (fd  * Hk + fh ) * Wk;
    a.rCF = (cdI * Hk + fh ) * Wk;
    a.rFC = (fd  * Hk + chI) * Wk;
    a.rCC = (cdI * Hk + chI) * Wk;
    return a;
}

__global__ __launch_bounds__(256)
void resampler_kernel(const float4* __restrict__ vol,     // [B,D,H,W] of float4
                      const float*  __restrict__ coords,  // [NPTS,3]
                      float4*       __restrict__ out)     // [NPTS] of float4
{
    unsigned long long polL = pol_evict_last();
    unsigned long long polF = pol_evict_first();

    int t = blockIdx.x * blockDim.x + threadIdx.x;        // exact-fit grid
    int q = t >> 1;                                       // pair index in [0, NPTS/2)
    int s = t & 1;                                        // 0 = floor-W, 1 = ceil-W

    int p0 = q;                    // batch 0
    int p1 = q + PTS_PER_BATCH;    // batch 1 (same spatial offset)

    PtAddr a0 = make_addr(vol, coords, p0, 0,     s, polF);
    PtAddr a1 = make_addr(vol, coords, p1, VOLSZ, s, polF);

    // 8 gathers back-to-back: MLP=8 per lane; lane pairs share 128B lines.
    float4 s0FF = ldg_vol(a0.q + a0.rFF, polL);
    float4 s0CF = ldg_vol(a0.q + a0.rCF, polL);
    float4 s0FC = ldg_vol(a0.q + a0.rFC, polL);
    float4 s0CC = ldg_vol(a0.q + a0.rCC, polL);
    float4 s1FF = ldg_vol(a1.q + a1.rFF, polL);
    float4 s1CF = ldg_vol(a1.q + a1.rCF, polL);
    float4 s1FC = ldg_vol(a1.q + a1.rFC, polL);
    float4 s1CC = ldg_vol(a1.q + a1.rCC, polL);

    // Point 0: bilinear H,D at fixed W, exchange, W-blend.
    float4 e0 = f4_fma2(s0FF, a0.w1h, s0FC, a0.w0h);
    float4 e1 = f4_fma2(s0CF, a0.w1h, s0CC, a0.w0h);
    float4 c0 = f4_fma2(e0, a0.w1d, e1, a0.w0d);

    float4 o0;
    o0.x = __shfl_xor_sync(0xffffffffu, c0.x, 1);
    o0.y = __shfl_xor_sync(0xffffffffu, c0.y, 1);
    o0.z = __shfl_xor_sync(0xffffffffu, c0.z, 1);
    o0.w = __shfl_xor_sync(0xffffffffu, c0.w, 1);

    // Point 1.
    float4 f0 = f4_fma2(s1FF, a1.w1h, s1FC, a1.w0h);
    float4 f1 = f4_fma2(s1CF, a1.w1h, s1CC, a1.w0h);
    float4 c1 = f4_fma2(f0, a1.w1d, f1, a1.w0d);

    float4 o1;
    o1.x = __shfl_xor_sync(0xffffffffu, c1.x, 1);
    o1.y = __shfl_xor_sync(0xffffffffu, c1.y, 1);
    o1.z = __shfl_xor_sync(0xffffffffu, c1.z, 1);
    o1.w = __shfl_xor_sync(0xffffffffu, c1.w, 1);

    if (s == 0) {
        stg_out(out + p0, f4_fma2(c0, a0.w1w, o0, a0.w0w));
        stg_out(out + p1, f4_fma2(c1, a1.w1w, o1, a1.w0w));
    }
}

extern "C" void kernel_launch(void* const* d_in, const int* in_sizes, int n_in,
                              void* d_out, int out_size) {
    const float4* vol    = (const float4*)d_in[0];   // inputs [B,D,H,W,4] fp32
    const float*  coords = (const float*)d_in[1];    // sample_coords [B,OD,OH,OW,3]
    float4*       out    = (float4*)d_out;

    const int threads = 256;
    const int blocks  = NPTS / threads;              // NPTS threads total, exact fit
    resampler_kernel<<<blocks, threads>>>(vol, coords, out);
}

// round 11
// speedup vs baseline: 1.2786x; 1.0065x over previous
#include <cuda_runtime.h>

// ResamplerLayer: trilinear resample of [B,D,H,W,C=4] fp32 volume at
// [B,OD,OH,OW,3] continuous coords (ZERO boundary: weights from CLAMPED
// corner indices). Output [B,OD,OH,OW,4] fp32.
//
// R4: 2 lanes per point (lane bit = floor-W / ceil-W) -> adjacent 16B pair
//     coalesces into one L1tex wavefront per gather instruction.
// R6: 2 points per thread (batch 0 + batch 1 at same spatial offset) -> 8
//     independent gathers in flight per lane.
// R8: L2 eviction policies: volume=evict_last (pin 67MB in 126MB L2),
//     coords=evict_first, stores=st.global.cs.
// R9: latency-bound with occ=65% (40 regs -> 6 CTAs/SM). Force
//     __launch_bounds__(256, 7) -> 36 regs -> 7 CTAs/SM (87.5% occ).

#define Bk   2
#define Dk   128
#define Hk   128
#define Wk   128
#define ODk  96
#define OHk  96
#define OWk  96

#define NPTS (Bk * ODk * OHk * OWk)          // 1,769,472
#define PTS_PER_BATCH (ODk * OHk * OWk)      // 884,736 == NPTS/2
#define VOLSZ (Dk * Hk * Wk)

__device__ __forceinline__ unsigned long long pol_evict_last() {
    unsigned long long p;
    asm("createpolicy.fractional.L2::evict_last.b64 %0, 1.0;" : "=l"(p));
    return p;
}

__device__ __forceinline__ unsigned long long pol_evict_first() {
    unsigned long long p;
    asm("createpolicy.fractional.L2::evict_first.b64 %0, 1.0;" : "=l"(p));
    return p;
}

// Volume gather: non-coherent load, pinned in L2 (evict_last policy).
__device__ __forceinline__ float4 ldg_vol(const float4* p, unsigned long long pol) {
    float4 v;
    asm volatile("ld.global.nc.L2::cache_hint.v4.f32 {%0,%1,%2,%3}, [%4], %5;"
                 : "=f"(v.x), "=f"(v.y), "=f"(v.z), "=f"(v.w)
                 : "l"(p), "l"(pol));
    return v;
}

// Coord load: streaming (evict_first policy).
__device__ __forceinline__ float ldg_coord(const float* p, unsigned long long pol) {
    float v;
    asm volatile("ld.global.nc.L2::cache_hint.f32 %0, [%1], %2;"
                 : "=f"(v) : "l"(p), "l"(pol));
    return v;
}

// Output store: cache-streaming.
__device__ __forceinline__ void stg_out(float4* p, float4 v) {
    asm volatile("st.global.cs.v4.f32 [%0], {%1,%2,%3,%4};"
                 :: "l"(p), "f"(v.x), "f"(v.y), "f"(v.z), "f"(v.w) : "memory");
}

__device__ __forceinline__ float4 f4_fma2(float4 a, float wa, float4 b, float wb) {
    float4 r;
    r.x = fmaf(a.x, wa, b.x * wb);
    r.y = fmaf(a.y, wa, b.y * wb);
    r.z = fmaf(a.z, wa, b.z * wb);
    r.w = fmaf(a.w, wa, b.w * wb);
    return r;
}

struct PtAddr {
    const float4* q;   // volume base + batch + this lane's W
    int rFF, rCF, rFC, rCC;
    float w0d, w1d, w0h, w1h, w0w, w1w;
};

__device__ __forceinline__ PtAddr make_addr(const float4* __restrict__ vol,
                                            const float* __restrict__ coords,
                                            int p, int batch_base, int s,
                                            unsigned long long polF) {
    const float* cp = coords + (size_t)p * 3;
    float cd = ldg_coord(cp + 0, polF);
    float ch = ldg_coord(cp + 1, polF);
    float cw = ldg_coord(cp + 2, polF);

    int fd0 = (int)floorf(cd);
    int fh0 = (int)floorf(ch);
    int fw0 = (int)floorf(cw);

    int fd  = min(max(fd0,     0), Dk - 1);
    int fh  = min(max(fh0,     0), Hk - 1);
    int fw  = min(max(fw0,     0), Wk - 1);
    int cdI = min(max(fd0 + 1, 0), Dk - 1);
    int chI = min(max(fh0 + 1, 0), Hk - 1);
    int cwI = min(max(fw0 + 1, 0), Wk - 1);

    PtAddr a;
    a.w0d = cd - (float)fd;    a.w1d = (float)cdI - cd;
    a.w0h = ch - (float)fh;    a.w1h = (float)chI - ch;
    a.w0w = cw - (float)fw;    a.w1w = (float)cwI - cw;

    int wsel = s ? cwI : fw;
    a.q = vol + batch_base + wsel;
    a.rFF = (fd  * Hk + fh ) * Wk;
    a.rCF = (cdI * Hk + fh ) * Wk;
    a.rFC = (fd  * Hk + chI) * Wk;
    a.rCC = (cdI * Hk + chI) * Wk;
    return a;
}

__global__ __launch_bounds__(256, 7)
void resampler_kernel(const float4* __restrict__ vol,     // [B,D,H,W] of float4
                      const float*  __restrict__ coords,  // [NPTS,3]
                      float4*       __restrict__ out)     // [NPTS] of float4
{
    unsigned long long polL = pol_evict_last();
    unsigned long long polF = pol_evict_first();

    int t = blockIdx.x * blockDim.x + threadIdx.x;        // exact-fit grid
    int q = t >> 1;                                       // pair index in [0, NPTS/2)
    int s = t & 1;                                        // 0 = floor-W, 1 = ceil-W

    int p0 = q;                    // batch 0
    int p1 = q + PTS_PER_BATCH;    // batch 1 (same spatial offset)

    PtAddr a0 = make_addr(vol, coords, p0, 0,     s, polF);
    PtAddr a1 = make_addr(vol, coords, p1, VOLSZ, s, polF);

    // 8 gathers back-to-back: MLP=8 per lane; lane pairs share 128B lines.
    float4 s0FF = ldg_vol(a0.q + a0.rFF, polL);
    float4 s0CF = ldg_vol(a0.q + a0.rCF, polL);
    float4 s0FC = ldg_vol(a0.q + a0.rFC, polL);
    float4 s0CC = ldg_vol(a0.q + a0.rCC, polL);
    float4 s1FF = ldg_vol(a1.q + a1.rFF, polL);
    float4 s1CF = ldg_vol(a1.q + a1.rCF, polL);
    float4 s1FC = ldg_vol(a1.q + a1.rFC, polL);
    float4 s1CC = ldg_vol(a1.q + a1.rCC, polL);

    // Point 0: bilinear H,D at fixed W, exchange, W-blend.
    float4 e0 = f4_fma2(s0FF, a0.w1h, s0FC, a0.w0h);
    float4 e1 = f4_fma2(s0CF, a0.w1h, s0CC, a0.w0h);
    float4 c0 = f4_fma2(e0, a0.w1d, e1, a0.w0d);

    float4 o0;
    o0.x = __shfl_xor_sync(0xffffffffu, c0.x, 1);
    o0.y = __shfl_xor_sync(0xffffffffu, c0.y, 1);
    o0.z = __shfl_xor_sync(0xffffffffu, c0.z, 1);
    o0.w = __shfl_xor_sync(0xffffffffu, c0.w, 1);

    // Point 1.
    float4 f0 = f4_fma2(s1FF, a1.w1h, s1FC, a1.w0h);
    float4 f1 = f4_fma2(s1CF, a1.w1h, s1CC, a1.w0h);
    float4 c1 = f4_fma2(f0, a1.w1d, f1, a1.w0d);

    float4 o1;
    o1.x = __shfl_xor_sync(0xffffffffu, c1.x, 1);
    o1.y = __shfl_xor_sync(0xffffffffu, c1.y, 1);
    o1.z = __shfl_xor_sync(0xffffffffu, c1.z, 1);
    o1.w = __shfl_xor_sync(0xffffffffu, c1.w, 1);

    if (s == 0) {
        stg_out(out + p0, f4_fma2(c0, a0.w1w, o0, a0.w0w));
        stg_out(out + p1, f4_fma2(c1, a1.w1w, o1, a1.w0w));
    }
}

extern "C" void kernel_launch(void* const* d_in, const int* in_sizes, int n_in,
                              void* d_out, int out_size) {
    const float4* vol    = (const float4*)d_in[0];   // inputs [B,D,H,W,4] fp32
    const float*  coords = (const float*)d_in[1];    // sample_coords [B,OD,OH,OW,3]
    float4*       out    = (float4*)d_out;

    const int threads = 256;
    const int blocks  = NPTS / threads;              // NPTS threads total, exact fit
    resampler_kernel<<<blocks, threads>>>(vol, coords, out);
}